// round 10
// baseline (speedup 1.0000x reference)
#include <cuda_runtime.h>
#include <cstdint>

#define LEAKY 0.2f
#define B_ 4
#define H_ 4
#define N_ 4096
#define F_ 64
#define U_ 32
#define BH_ (B_*H_)
#define NB_ 256   // value-quantized bins per (b,h)

// ---------------- scratch (device globals; no allocations) ----------------
__device__ float g_feats[BH_ * N_ * U_];   // [bh][n][u]
__device__ float g_s[BH_ * N_];            // a_self (original order)
__device__ float g_t[BH_ * N_];            // a_neigh (original order)
__device__ float g_ea[BH_ * N_];           // exp(LEAKY*s) per query
__device__ float g_eb[BH_ * N_];           // exp(s) per query
__device__ float g_tso[BH_ * N_];          // t in bucket-scatter order
__device__ float g_w1so[BH_ * N_];         // exp(t) in scatter order
__device__ float g_w2so[BH_ * N_];         // exp(LEAKY*t) in scatter order
__device__ int   g_perm[BH_ * N_];         // scatter order -> original index
__device__ int   g_binstart[BH_ * (NB_ + 1)];
__device__ float g_lo[BH_], g_scale[BH_];
__device__ float g_T1t[BH_ * U_ * NB_];    // per-bin sums of w1*feats, [bh][u][bin]
__device__ float g_T2t[BH_ * U_ * NB_];    // per-bin sums of w2*feats, [bh][u][bin]
__device__ float g_O1[BH_ * NB_ * U_];     // exclusive bin offsets [bh][bin][u]
__device__ float g_O2[BH_ * NB_ * U_];
__device__ float g_C1[BH_ * NB_];          // per-bin scalar sums of w1
__device__ float g_C2[BH_ * NB_];          // per-bin scalar sums of w2
__device__ float g_Sb1[BH_ * NB_];         // exclusive scalar offsets
__device__ float g_Sb2[BH_ * NB_];
__device__ float g_Stot1[BH_];             // total w1 scalar
__device__ float g_Ptot1[BH_ * U_];        // total w1*feats vector

// ============================================================
// k1: feats = x@K per head; s,t projections; per-query exps.
// grid (N/128, BH), block 128
// ============================================================
__global__ void __launch_bounds__(128) k1_feats(
        const float* __restrict__ x,
        const float* __restrict__ kern,
        const float* __restrict__ att_s,
        const float* __restrict__ att_n) {
    __shared__ float  xs[128][F_ + 1];
    __shared__ float4 ks4[F_ * (U_ / 4)];
    __shared__ float  as_s[U_], as_n[U_];

    const int bh = blockIdx.y;
    const int b = bh / H_, h = bh % H_;
    const int tid = threadIdx.x;

    const float4* ksrc = (const float4*)(kern + (size_t)h * F_ * U_);
    for (int i = tid; i < F_ * (U_ / 4); i += 128) ks4[i] = ksrc[i];
    if (tid < U_) { as_s[tid] = att_s[h * U_ + tid]; as_n[tid] = att_n[h * U_ + tid]; }

    const int n0 = blockIdx.x * 128;
    const float* xb = x + ((size_t)b * N_ + n0) * F_;
    for (int i = tid; i < 128 * F_; i += 128) xs[i >> 6][i & 63] = xb[i];
    __syncthreads();

    float acc[U_];
#pragma unroll
    for (int u = 0; u < U_; u++) acc[u] = 0.f;

#pragma unroll 4
    for (int f = 0; f < F_; f++) {
        const float xv = xs[tid][f];
#pragma unroll
        for (int u4 = 0; u4 < U_ / 4; u4++) {
            const float4 kv = ks4[f * (U_ / 4) + u4];
            acc[u4 * 4 + 0] += xv * kv.x;
            acc[u4 * 4 + 1] += xv * kv.y;
            acc[u4 * 4 + 2] += xv * kv.z;
            acc[u4 * 4 + 3] += xv * kv.w;
        }
    }

    const int n = n0 + tid;
    float* fo = g_feats + ((size_t)bh * N_ + n) * U_;
#pragma unroll
    for (int u4 = 0; u4 < U_ / 4; u4++) {
        ((float4*)fo)[u4] = make_float4(acc[u4*4], acc[u4*4+1], acc[u4*4+2], acc[u4*4+3]);
    }
    float s = 0.f, t = 0.f;
#pragma unroll
    for (int u = 0; u < U_; u++) { s += acc[u] * as_s[u]; t += acc[u] * as_n[u]; }
    g_s[bh * N_ + n]  = s;
    g_t[bh * N_ + n]  = t;
    g_ea[bh * N_ + n] = expf(LEAKY * s);
    g_eb[bh * N_ + n] = expf(s);
}

// ============================================================
// k2b: per-(b,h) value bucketing + exp-at-scatter.
// grid BH, block 1024 (4 elements/thread)
// ============================================================
__global__ void __launch_bounds__(1024, 1) k2b_bucket() {
    __shared__ int   cnt[NB_];
    __shared__ float red[64];
    __shared__ int   wsum[NB_ / 32];
    __shared__ float slo, shi;

    const int bh = blockIdx.x;
    const int tid = threadIdx.x;
    const int lane = tid & 31, w = tid >> 5;

    float tv[4]; int bins[4];
    float mn = 1e30f, mx = -1e30f;
#pragma unroll
    for (int e = 0; e < 4; e++) {
        tv[e] = g_t[bh * N_ + tid * 4 + e];
        mn = fminf(mn, tv[e]); mx = fmaxf(mx, tv[e]);
    }
#pragma unroll
    for (int off = 16; off >= 1; off >>= 1) {
        mn = fminf(mn, __shfl_xor_sync(0xffffffffu, mn, off));
        mx = fmaxf(mx, __shfl_xor_sync(0xffffffffu, mx, off));
    }
    if (lane == 0) { red[w] = mn; red[32 + w] = mx; }
    if (tid < NB_) cnt[tid] = 0;
    __syncthreads();
    if (w == 0) {
        float m1 = red[lane], m2 = red[32 + lane];
#pragma unroll
        for (int off = 16; off >= 1; off >>= 1) {
            m1 = fminf(m1, __shfl_xor_sync(0xffffffffu, m1, off));
            m2 = fmaxf(m2, __shfl_xor_sync(0xffffffffu, m2, off));
        }
        if (lane == 0) { slo = m1; shi = m2; }
    }
    __syncthreads();
    const float lo = slo;
    const float scale = (shi > lo) ? (float)NB_ * 0.999999f / (shi - lo) : 0.f;

#pragma unroll
    for (int e = 0; e < 4; e++) {
        int bi = (int)((tv[e] - lo) * scale);
        bi = min(NB_ - 1, max(0, bi));
        bins[e] = bi;
        atomicAdd(&cnt[bi], 1);
    }
    __syncthreads();

    // exclusive scan of cnt[NB_] (threads 0..NB_-1)
    int cval = 0, inc = 0;
    if (tid < NB_) {
        cval = cnt[tid];
        inc = cval;
#pragma unroll
        for (int off = 1; off < 32; off <<= 1) {
            const int o = __shfl_up_sync(0xffffffffu, inc, off);
            if (lane >= off) inc += o;
        }
        if (lane == 31) wsum[w] = inc;
    }
    __syncthreads();
    if (tid == 0) {
        int run = 0;
#pragma unroll
        for (int k = 0; k < NB_ / 32; k++) { const int xk = wsum[k]; wsum[k] = run; run += xk; }
    }
    __syncthreads();
    if (tid < NB_) {
        const int ex = inc - cval + wsum[w];
        g_binstart[bh * (NB_ + 1) + tid] = ex;
        cnt[tid] = ex;          // reuse as running offsets
    }
    if (tid == 0) {
        g_binstart[bh * (NB_ + 1) + NB_] = N_;
        g_lo[bh] = lo; g_scale[bh] = scale;
    }
    __syncthreads();

#pragma unroll
    for (int e = 0; e < 4; e++) {
        const int pos = atomicAdd(&cnt[bins[e]], 1);
        g_perm[bh * N_ + pos]  = tid * 4 + e;
        g_tso[bh * N_ + pos]   = tv[e];
        g_w1so[bh * N_ + pos]  = expf(tv[e]);
        g_w2so[bh * N_ + pos]  = expf(LEAKY * tv[e]);
    }
}

// ============================================================
// k3: per-bin sums of w1*feats / w2*feats + scalar sums.
// Pure load/FMA (no exp). Vector totals transposed [bh][u][bin].
// grid (BH, NB/8), block 256 = 8 warps; warp -> bin, lane -> u.
// ============================================================
__global__ void __launch_bounds__(256) k3_bin_sums() {
    const int bh = blockIdx.x;
    const int w = threadIdx.x >> 5, lane = threadIdx.x & 31;
    const int bin = blockIdx.y * 8 + w;

    const int js = __ldg(&g_binstart[bh * (NB_ + 1) + bin]);
    const int je = __ldg(&g_binstart[bh * (NB_ + 1) + bin + 1]);
    const float* fe = g_feats + (size_t)bh * N_ * U_;

    float a1 = 0.f, a2 = 0.f, c1 = 0.f, c2 = 0.f;
    for (int j = js; j < je; j++) {
        const int p = __ldg(&g_perm[bh * N_ + j]);
        const float w1 = __ldg(&g_w1so[bh * N_ + j]);
        const float w2 = __ldg(&g_w2so[bh * N_ + j]);
        const float v = __ldg(&fe[p * U_ + lane]);
        a1 += w1 * v; a2 += w2 * v; c1 += w1; c2 += w2;
    }
    const size_t ti = ((size_t)bh * U_ + lane) * NB_ + bin;   // transposed
    g_T1t[ti] = a1;
    g_T2t[ti] = a2;
    if (lane == 0) { g_C1[bh * NB_ + bin] = c1; g_C2[bh * NB_ + bin] = c2; }
}

// ============================================================
// dual exclusive scan of two contiguous NB_-float rows.
// block = 64 threads, 4 elements/thread via float4.
// ============================================================
__device__ __forceinline__ void dual_scan_256(
        const float* __restrict__ in1, const float* __restrict__ in2,
        float* __restrict__ out1, float* __restrict__ out2, int ostride,
        float* __restrict__ tot1) {
    __shared__ float ws1[2], ws2[2];
    const int tid = threadIdx.x, lane = tid & 31, w = tid >> 5;

    const float4 a = ((const float4*)in1)[tid];
    const float4 b = ((const float4*)in2)[tid];
    float l1[4], l2[4];
    l1[0] = a.x; l1[1] = l1[0] + a.y; l1[2] = l1[1] + a.z; l1[3] = l1[2] + a.w;
    l2[0] = b.x; l2[1] = l2[0] + b.y; l2[2] = l2[1] + b.z; l2[3] = l2[2] + b.w;
    const float t1 = l1[3], t2 = l2[3];
    float i1 = t1, i2 = t2;
#pragma unroll
    for (int off = 1; off < 32; off <<= 1) {
        const float x1 = __shfl_up_sync(0xffffffffu, i1, off);
        const float x2 = __shfl_up_sync(0xffffffffu, i2, off);
        if (lane >= off) { i1 += x1; i2 += x2; }
    }
    if (lane == 31) { ws1[w] = i1; ws2[w] = i2; }
    __syncthreads();
    const float off1 = (w == 1) ? ws1[0] : 0.f;
    const float off2 = (w == 1) ? ws2[0] : 0.f;
    const float e1 = off1 + i1 - t1;   // exclusive start for this thread
    const float e2 = off2 + i2 - t2;
    const int base = 4 * tid;
    out1[(base + 0) * ostride] = e1;
    out1[(base + 1) * ostride] = e1 + l1[0];
    out1[(base + 2) * ostride] = e1 + l1[1];
    out1[(base + 3) * ostride] = e1 + l1[2];
    out2[(base + 0) * ostride] = e2;
    out2[(base + 1) * ostride] = e2 + l2[0];
    out2[(base + 2) * ostride] = e2 + l2[1];
    out2[(base + 3) * ostride] = e2 + l2[2];
    if (tot1 && tid == 63) *tot1 = off1 + i1;   // grand total of array 1
}

// ============================================================
// k3b: grid = BH*33, block 64.
// r<32: scan of T1t/T2t row (bh,u) -> O1/O2 [bh][bin][u] + Ptot1.
// r==32: scalar scans C1->Sb1 (+Stot1), C2->Sb2.
// ============================================================
__global__ void __launch_bounds__(64) k3b_scan() {
    const int bh = blockIdx.x / 33;
    const int r  = blockIdx.x % 33;

    if (r < 32) {
        const size_t bi = ((size_t)bh * U_ + r) * NB_;
        dual_scan_256(g_T1t + bi, g_T2t + bi,
                      g_O1 + (size_t)bh * NB_ * U_ + r,
                      g_O2 + (size_t)bh * NB_ * U_ + r,
                      U_,
                      &g_Ptot1[bh * U_ + r]);
    } else {
        dual_scan_256(g_C1 + bh * NB_, g_C2 + bh * NB_,
                      g_Sb1 + bh * NB_, g_Sb2 + bh * NB_, 1,
                      &g_Stot1[bh]);
    }
}

// ============================================================
// k4: per-node combine. warp -> one n, lane -> u. Pure load/FMA.
// grid BH*N/8, block 256
// ============================================================
__global__ void __launch_bounds__(256) k4_output(
        const float* __restrict__ biases, float* __restrict__ out) {
    const int gw = blockIdx.x * 8 + (threadIdx.x >> 5);
    const int lane = threadIdx.x & 31;
    const int bh = gw >> 12;        // / N_
    const int n = gw & (N_ - 1);
    const int b = bh >> 2, h = bh & (H_ - 1);

    const float c = g_s[bh * N_ + n];
    const float th = -c;
    const float lo = __ldg(&g_lo[bh]);
    const float scale = __ldg(&g_scale[bh]);
    int bq = (int)((th - lo) * scale);
    bq = min(NB_ - 1, max(0, bq));

    float p1 = __ldg(&g_O1[((size_t)bh * NB_ + bq) * U_ + lane]);
    float p2 = __ldg(&g_O2[((size_t)bh * NB_ + bq) * U_ + lane]);
    float s1 = __ldg(&g_Sb1[bh * NB_ + bq]);
    float s2 = __ldg(&g_Sb2[bh * NB_ + bq]);

    const int js = __ldg(&g_binstart[bh * (NB_ + 1) + bq]);
    const int je = __ldg(&g_binstart[bh * (NB_ + 1) + bq + 1]);
    const float* fe = g_feats + (size_t)bh * N_ * U_;
    for (int j = js; j < je; j++) {
        const float tv = __ldg(&g_tso[bh * N_ + j]);
        if (tv < th) {
            const float w1 = __ldg(&g_w1so[bh * N_ + j]);
            const float w2 = __ldg(&g_w2so[bh * N_ + j]);
            const int p = __ldg(&g_perm[bh * N_ + j]);
            const float v = __ldg(&fe[p * U_ + lane]);
            p1 += w1 * v; p2 += w2 * v; s1 += w1; s2 += w2;
        }
    }

    const float ea = __ldg(&g_ea[bh * N_ + n]);
    const float eb = __ldg(&g_eb[bh * N_ + n]);
    const float S1t = __ldg(&g_Stot1[bh]);
    const float pt1 = __ldg(&g_Ptot1[bh * U_ + lane]);

    const float Z = ea * s2 + eb * (S1t - s1);
    const float num = ea * p2 + eb * (pt1 - p1);
    const float val = num / Z + __ldg(&biases[h * U_ + lane]);

    out[((size_t)b * N_ + n) * (H_ * U_) + h * U_ + lane] = fmaxf(val, 0.f);
}

// ============================================================
extern "C" void kernel_launch(void* const* d_in, const int* in_sizes, int n_in,
                              void* d_out, int out_size) {
    const float* x      = (const float*)d_in[0];
    const float* kern   = (const float*)d_in[1];
    const float* att_s  = (const float*)d_in[2];
    const float* att_n  = (const float*)d_in[3];
    const float* biases = (const float*)d_in[4];
    float* out = (float*)d_out;

    k1_feats<<<dim3(N_ / 128, BH_), 128>>>(x, kern, att_s, att_n);
    k2b_bucket<<<BH_, 1024>>>();
    k3_bin_sums<<<dim3(BH_, NB_ / 8), 256>>>();
    k3b_scan<<<BH_ * 33, 64>>>();
    k4_output<<<(BH_ * N_) / 8, 256>>>(biases, out);
}

// round 12
// speedup vs baseline: 1.3010x; 1.3010x over previous
#include <cuda_runtime.h>
#include <cstdint>

#define LEAKY 0.2f
#define B_ 4
#define H_ 4
#define N_ 4096
#define F_ 64
#define U_ 32
#define BH_ (B_*H_)
#define NB_ 1024      // value-quantized bins per (b,h)
#define NSEG_ 32      // 32 segments of 32 bins

// ---------------- scratch (device globals; no allocations) ----------------
__device__ float g_feats[BH_ * N_ * U_];     // [bh][n][u]
__device__ float g_s[BH_ * N_];              // a_self (original order)
__device__ float g_t[BH_ * N_];              // a_neigh (original order)
__device__ float g_ea[BH_ * N_];             // exp(LEAKY*s) per query
__device__ float g_eb[BH_ * N_];             // exp(s) per query
__device__ float g_tso[BH_ * N_];            // t in bucket-scatter order
__device__ float g_w1so[BH_ * N_];           // exp(t) scatter order
__device__ float g_w2so[BH_ * N_];           // exp(LEAKY*t) scatter order
__device__ int   g_perm[BH_ * N_];           // scatter order -> original index
__device__ int   g_binstart[BH_ * (NB_ + 1)];
__device__ float g_lo[BH_], g_scale[BH_];
__device__ float g_O1[BH_ * NB_ * U_];       // within-segment exclusive vec prefix [bh][bin][u]
__device__ float g_O2[BH_ * NB_ * U_];
__device__ float g_Seg1[BH_ * NSEG_ * U_];   // exclusive segment offsets [bh][seg][u]
__device__ float g_Seg2[BH_ * NSEG_ * U_];
__device__ float g_Sb1[BH_ * NB_];           // within-segment exclusive scalar prefix
__device__ float g_Sb2[BH_ * NB_];
__device__ float g_SegSb1[BH_ * NSEG_];      // exclusive scalar segment offsets
__device__ float g_SegSb2[BH_ * NSEG_];
__device__ float g_Stot1[BH_];               // total w1 scalar
__device__ float g_Ptot1[BH_ * U_];          // total w1*feats vector

// ============================================================
// k1: feats = x@K per head; s,t projections; per-query exps.
// grid (N/128, BH), block 128
// ============================================================
__global__ void __launch_bounds__(128) k1_feats(
        const float* __restrict__ x,
        const float* __restrict__ kern,
        const float* __restrict__ att_s,
        const float* __restrict__ att_n) {
    __shared__ float  xs[128][F_ + 1];
    __shared__ float4 ks4[F_ * (U_ / 4)];
    __shared__ float  as_s[U_], as_n[U_];

    const int bh = blockIdx.y;
    const int b = bh / H_, h = bh % H_;
    const int tid = threadIdx.x;

    const float4* ksrc = (const float4*)(kern + (size_t)h * F_ * U_);
    for (int i = tid; i < F_ * (U_ / 4); i += 128) ks4[i] = ksrc[i];
    if (tid < U_) { as_s[tid] = att_s[h * U_ + tid]; as_n[tid] = att_n[h * U_ + tid]; }

    const int n0 = blockIdx.x * 128;
    const float* xb = x + ((size_t)b * N_ + n0) * F_;
    for (int i = tid; i < 128 * F_; i += 128) xs[i >> 6][i & 63] = xb[i];
    __syncthreads();

    float acc[U_];
#pragma unroll
    for (int u = 0; u < U_; u++) acc[u] = 0.f;

#pragma unroll 4
    for (int f = 0; f < F_; f++) {
        const float xv = xs[tid][f];
#pragma unroll
        for (int u4 = 0; u4 < U_ / 4; u4++) {
            const float4 kv = ks4[f * (U_ / 4) + u4];
            acc[u4 * 4 + 0] += xv * kv.x;
            acc[u4 * 4 + 1] += xv * kv.y;
            acc[u4 * 4 + 2] += xv * kv.z;
            acc[u4 * 4 + 3] += xv * kv.w;
        }
    }

    const int n = n0 + tid;
    float* fo = g_feats + ((size_t)bh * N_ + n) * U_;
#pragma unroll
    for (int u4 = 0; u4 < U_ / 4; u4++) {
        ((float4*)fo)[u4] = make_float4(acc[u4*4], acc[u4*4+1], acc[u4*4+2], acc[u4*4+3]);
    }
    float s = 0.f, t = 0.f;
#pragma unroll
    for (int u = 0; u < U_; u++) { s += acc[u] * as_s[u]; t += acc[u] * as_n[u]; }
    g_s[bh * N_ + n]  = s;
    g_t[bh * N_ + n]  = t;
    g_ea[bh * N_ + n] = expf(LEAKY * s);
    g_eb[bh * N_ + n] = expf(s);
}

// ============================================================
// kmid: fused bucket + bin sums + prefix (one block per bh).
// block 1024 threads; all intermediates in dynamic smem (~82KB).
// Warp-per-bin with lane=u: feats gathers and O-stores are
// 128B coalesced; running vector prefix lives across lanes.
// ============================================================
__global__ void __launch_bounds__(1024, 1) kmid() {
    extern __shared__ unsigned char dsm[];
    float* tso_s  = (float*)dsm;                 // 4096
    float* w1_s   = tso_s + N_;                  // 4096
    float* w2_s   = w1_s + N_;                   // 4096
    int*   perm_s = (int*)(w2_s + N_);           // 4096
    int*   bs_s   = perm_s + N_;                 // 1025 (+pad 31)
    int*   cnt    = bs_s + NB_ + 32;             // 1024
    float* seg1   = (float*)(cnt + NB_);         // 32*32
    float* seg2   = seg1 + NSEG_ * U_;           // 32*32
    float* segc1  = seg2 + NSEG_ * U_;           // 32
    float* segc2  = segc1 + NSEG_;               // 32

    __shared__ float red[64];
    __shared__ int   wsum[32];
    __shared__ float slo, shi;

    const int bh = blockIdx.x;
    const int tid = threadIdx.x;
    const int lane = tid & 31, w = tid >> 5;

    // ---- Phase A: load t, min/max, histogram, scan, scatter ----
    float tv[4]; int bins[4];
    float mn = 1e30f, mx = -1e30f;
#pragma unroll
    for (int e = 0; e < 4; e++) {
        tv[e] = g_t[bh * N_ + tid * 4 + e];
        mn = fminf(mn, tv[e]); mx = fmaxf(mx, tv[e]);
    }
#pragma unroll
    for (int off = 16; off >= 1; off >>= 1) {
        mn = fminf(mn, __shfl_xor_sync(0xffffffffu, mn, off));
        mx = fmaxf(mx, __shfl_xor_sync(0xffffffffu, mx, off));
    }
    if (lane == 0) { red[w] = mn; red[32 + w] = mx; }
    cnt[tid] = 0;
    __syncthreads();
    if (w == 0) {
        float m1 = red[lane], m2 = red[32 + lane];
#pragma unroll
        for (int off = 16; off >= 1; off >>= 1) {
            m1 = fminf(m1, __shfl_xor_sync(0xffffffffu, m1, off));
            m2 = fmaxf(m2, __shfl_xor_sync(0xffffffffu, m2, off));
        }
        if (lane == 0) { slo = m1; shi = m2; }
    }
    __syncthreads();
    const float lo = slo;
    const float scale = (shi > lo) ? (float)NB_ * 0.999999f / (shi - lo) : 0.f;

#pragma unroll
    for (int e = 0; e < 4; e++) {
        int bi = (int)((tv[e] - lo) * scale);
        bi = min(NB_ - 1, max(0, bi));
        bins[e] = bi;
        atomicAdd(&cnt[bi], 1);
    }
    __syncthreads();

    const int cval = cnt[tid];
    int inc = cval;
#pragma unroll
    for (int off = 1; off < 32; off <<= 1) {
        const int o = __shfl_up_sync(0xffffffffu, inc, off);
        if (lane >= off) inc += o;
    }
    if (lane == 31) wsum[w] = inc;
    __syncthreads();
    if (tid == 0) {
        int run = 0;
#pragma unroll
        for (int k = 0; k < 32; k++) { const int xk = wsum[k]; wsum[k] = run; run += xk; }
    }
    __syncthreads();
    const int ex = inc - cval + wsum[w];
    bs_s[tid] = ex;
    cnt[tid] = ex;                 // running scatter offsets
    g_binstart[bh * (NB_ + 1) + tid] = ex;
    if (tid == 0) {
        bs_s[NB_] = N_;
        g_binstart[bh * (NB_ + 1) + NB_] = N_;
        g_lo[bh] = lo; g_scale[bh] = scale;
    }
    __syncthreads();

#pragma unroll
    for (int e = 0; e < 4; e++) {
        const int pos = atomicAdd(&cnt[bins[e]], 1);
        perm_s[pos] = tid * 4 + e;
        tso_s[pos]  = tv[e];
        w1_s[pos]   = expf(tv[e]);
        w2_s[pos]   = expf(LEAKY * tv[e]);
    }
    __syncthreads();

    // coalesced copy of scatter arrays to global (k4 reads them)
#pragma unroll
    for (int k = 0; k < 4; k++) {
        const int i = tid + k * 1024;
        g_tso[bh * N_ + i]  = tso_s[i];
        g_w1so[bh * N_ + i] = w1_s[i];
        g_w2so[bh * N_ + i] = w2_s[i];
        g_perm[bh * N_ + i] = perm_s[i];
    }

    // ---- Phase B: warp w handles bins [32w, 32w+32); lane = u ----
    const float* fe = g_feats + (size_t)bh * N_ * U_;
    float r1 = 0.f, r2 = 0.f;      // running vector prefix (per-lane = per-u)
    float rc1 = 0.f, rc2 = 0.f;    // running scalar prefix (broadcast-replicated)
    for (int i = 0; i < 32; i++) {
        const int bin = w * 32 + i;
        const int js = bs_s[bin], je = bs_s[bin + 1];
        float a1 = 0.f, a2 = 0.f, c1 = 0.f, c2 = 0.f;
        for (int j = js; j < je; j++) {
            const float w1v = w1_s[j];
            const float w2v = w2_s[j];
            const int p = perm_s[j];
            const float v = __ldg(&fe[p * U_ + lane]);
            a1 += w1v * v; a2 += w2v * v; c1 += w1v; c2 += w2v;
        }
        const size_t oi = ((size_t)bh * NB_ + bin) * U_ + lane;
        g_O1[oi] = r1;             // exclusive within segment
        g_O2[oi] = r2;
        if (lane == 0) {
            g_Sb1[bh * NB_ + bin] = rc1;
            g_Sb2[bh * NB_ + bin] = rc2;
        }
        r1 += a1; r2 += a2; rc1 += c1; rc2 += c2;
    }
    seg1[w * U_ + lane] = r1;
    seg2[w * U_ + lane] = r2;
    if (lane == 0) { segc1[w] = rc1; segc2[w] = rc2; }
    __syncthreads();

    // ---- Phase C: exclusive segment offsets (warp w -> segment w) ----
    float o1 = 0.f, o2 = 0.f, oc1 = 0.f, oc2 = 0.f;
    for (int s = 0; s < w; s++) {
        o1 += seg1[s * U_ + lane];
        o2 += seg2[s * U_ + lane];
        oc1 += segc1[s];
        oc2 += segc2[s];
    }
    const size_t si = ((size_t)bh * NSEG_ + w) * U_ + lane;
    g_Seg1[si] = o1;
    g_Seg2[si] = o2;
    if (lane == 0) {
        g_SegSb1[bh * NSEG_ + w] = oc1;
        g_SegSb2[bh * NSEG_ + w] = oc2;
    }
    if (w == 31) {
        g_Ptot1[bh * U_ + lane] = o1 + seg1[31 * U_ + lane];
        if (lane == 0) g_Stot1[bh] = oc1 + segc1[31];
    }
}

// ============================================================
// k4: per-node combine. warp -> one n, lane -> u. Pure load/FMA.
// grid BH*N/8, block 256
// ============================================================
__global__ void __launch_bounds__(256) k4_output(
        const float* __restrict__ biases, float* __restrict__ out) {
    const int gw = blockIdx.x * 8 + (threadIdx.x >> 5);
    const int lane = threadIdx.x & 31;
    const int bh = gw >> 12;        // / N_
    const int n = gw & (N_ - 1);
    const int b = bh >> 2, h = bh & (H_ - 1);

    const float c = g_s[bh * N_ + n];
    const float th = -c;
    const float lo = __ldg(&g_lo[bh]);
    const float scale = __ldg(&g_scale[bh]);
    int bq = (int)((th - lo) * scale);
    bq = min(NB_ - 1, max(0, bq));
    const int sq = bq >> 5;

    float p1 = __ldg(&g_O1[((size_t)bh * NB_ + bq) * U_ + lane])
             + __ldg(&g_Seg1[((size_t)bh * NSEG_ + sq) * U_ + lane]);
    float p2 = __ldg(&g_O2[((size_t)bh * NB_ + bq) * U_ + lane])
             + __ldg(&g_Seg2[((size_t)bh * NSEG_ + sq) * U_ + lane]);
    float s1 = __ldg(&g_Sb1[bh * NB_ + bq]) + __ldg(&g_SegSb1[bh * NSEG_ + sq]);
    float s2 = __ldg(&g_Sb2[bh * NB_ + bq]) + __ldg(&g_SegSb2[bh * NSEG_ + sq]);

    const int js = __ldg(&g_binstart[bh * (NB_ + 1) + bq]);
    const int je = __ldg(&g_binstart[bh * (NB_ + 1) + bq + 1]);
    const float* fe = g_feats + (size_t)bh * N_ * U_;
    for (int j = js; j < je; j++) {
        const float tv = __ldg(&g_tso[bh * N_ + j]);
        if (tv < th) {
            const float w1 = __ldg(&g_w1so[bh * N_ + j]);
            const float w2 = __ldg(&g_w2so[bh * N_ + j]);
            const int p = __ldg(&g_perm[bh * N_ + j]);
            const float v = __ldg(&fe[p * U_ + lane]);
            p1 += w1 * v; p2 += w2 * v; s1 += w1; s2 += w2;
        }
    }

    const float ea = __ldg(&g_ea[bh * N_ + n]);
    const float eb = __ldg(&g_eb[bh * N_ + n]);
    const float S1t = __ldg(&g_Stot1[bh]);
    const float pt1 = __ldg(&g_Ptot1[bh * U_ + lane]);

    const float Z = ea * s2 + eb * (S1t - s1);
    const float num = ea * p2 + eb * (pt1 - p1);
    const float val = num / Z + __ldg(&biases[h * U_ + lane]);

    out[((size_t)b * N_ + n) * (H_ * U_) + h * U_ + lane] = fmaxf(val, 0.f);
}

// ============================================================
extern "C" void kernel_launch(void* const* d_in, const int* in_sizes, int n_in,
                              void* d_out, int out_size) {
    const float* x      = (const float*)d_in[0];
    const float* kern   = (const float*)d_in[1];
    const float* att_s  = (const float*)d_in[2];
    const float* att_n  = (const float*)d_in[3];
    const float* biases = (const float*)d_in[4];
    float* out = (float*)d_out;

    // dynamic smem for kmid: 3*N floats + N ints + (NB+32+NB) ints + 2*32*32 + 64 floats
    const int kmid_smem = (3 * N_ + N_ + (NB_ + 32) + NB_ + 2 * NSEG_ * U_ + 2 * NSEG_) * 4;
    cudaFuncSetAttribute(kmid, cudaFuncAttributeMaxDynamicSharedMemorySize, kmid_smem);

    k1_feats<<<dim3(N_ / 128, BH_), 128>>>(x, kern, att_s, att_n);
    kmid<<<BH_, 1024, kmid_smem>>>();
    k4_output<<<(BH_ * N_) / 8, 256>>>(biases, out);
}

// round 13
// speedup vs baseline: 1.6226x; 1.2472x over previous
#include <cuda_runtime.h>
#include <cstdint>

#define LEAKY 0.2f
#define B_ 4
#define H_ 4
#define N_ 4096
#define F_ 64
#define U_ 32
#define BH_ (B_*H_)
#define NB_ 1024      // value-quantized bins per (b,h)
#define NSEG_ 32      // 32 segments of 32 bins
#define ROWS_ 64      // k1 tile rows

// ---------------- scratch (device globals; no allocations) ----------------
__device__ float g_feats[BH_ * N_ * U_];     // [bh][n][u]
__device__ float g_s[BH_ * N_];              // a_self (original order)
__device__ float g_t[BH_ * N_];              // a_neigh (original order)
__device__ float g_ea[BH_ * N_];             // exp(LEAKY*s) per query
__device__ float g_eb[BH_ * N_];             // exp(s) per query
__device__ float g_tso[BH_ * N_];            // t in bucket-scatter order
__device__ float g_w1so[BH_ * N_];           // exp(t) scatter order
__device__ float g_w2so[BH_ * N_];           // exp(LEAKY*t) scatter order
__device__ int   g_perm[BH_ * N_];           // scatter order -> original index
__device__ int   g_binstart[BH_ * (NB_ + 1)];
__device__ float g_lo[BH_], g_scale[BH_];
__device__ float g_T1[BH_ * NB_ * U_];       // per-bin vec sums [bh][bin][u]
__device__ float g_T2[BH_ * NB_ * U_];
__device__ float g_O1[BH_ * NB_ * U_];       // within-segment exclusive vec prefix
__device__ float g_O2[BH_ * NB_ * U_];
__device__ float g_Seg1[BH_ * NSEG_ * U_];   // exclusive segment offsets [bh][seg][u]
__device__ float g_Seg2[BH_ * NSEG_ * U_];
__device__ float g_C1[BH_ * NB_];            // per-bin scalar sums
__device__ float g_C2[BH_ * NB_];
__device__ float g_Sb1[BH_ * NB_];           // within-segment exclusive scalar prefix
__device__ float g_Sb2[BH_ * NB_];
__device__ float g_SegSb1[BH_ * NSEG_];      // exclusive scalar segment offsets
__device__ float g_SegSb2[BH_ * NSEG_];
__device__ float g_Stot1[BH_];               // total w1 scalar
__device__ float g_Ptot1[BH_ * U_];          // total w1*feats vector

// ============================================================
// k1 v2: 64-row tiles, 4 threads/row (8 u's each).
// grid (N/64, BH), block 256. regs ~40, smem ~26KB -> high occ.
// ============================================================
__global__ void __launch_bounds__(256) k1_feats(
        const float* __restrict__ x,
        const float* __restrict__ kern,
        const float* __restrict__ att_s,
        const float* __restrict__ att_n) {
    __shared__ float  xs[ROWS_][F_ + 4];      // 64 x 68 floats
    __shared__ float4 ks4[F_ * (U_ / 4)];     // 8 KB
    __shared__ float  as_s[U_], as_n[U_];

    const int bh = blockIdx.y;
    const int b = bh / H_, h = bh % H_;
    const int tid = threadIdx.x;

    const float4* ksrc = (const float4*)(kern + (size_t)h * F_ * U_);
#pragma unroll
    for (int i = tid; i < F_ * (U_ / 4); i += 256) ks4[i] = ksrc[i];
    if (tid < U_) { as_s[tid] = att_s[h * U_ + tid]; as_n[tid] = att_n[h * U_ + tid]; }

    const int n0 = blockIdx.x * ROWS_;
    const float4* xb4 = (const float4*)(x + ((size_t)b * N_ + n0) * F_);
#pragma unroll
    for (int i = tid; i < ROWS_ * (F_ / 4); i += 256) {
        const int r = i >> 4, c = i & 15;
        *(float4*)&xs[r][c * 4] = xb4[i];
    }
    __syncthreads();

    const int row = tid >> 2;      // 0..63
    const int uq  = tid & 3;       // u base = uq*8

    float acc[8];
#pragma unroll
    for (int i = 0; i < 8; i++) acc[i] = 0.f;

#pragma unroll 8
    for (int f = 0; f < F_; f++) {
        const float xv = xs[row][f];
        const float4 k0 = ks4[f * 8 + uq * 2];
        const float4 k1 = ks4[f * 8 + uq * 2 + 1];
        acc[0] += xv * k0.x; acc[1] += xv * k0.y;
        acc[2] += xv * k0.z; acc[3] += xv * k0.w;
        acc[4] += xv * k1.x; acc[5] += xv * k1.y;
        acc[6] += xv * k1.z; acc[7] += xv * k1.w;
    }

    const int n = n0 + row;
    float* fo = g_feats + ((size_t)bh * N_ + n) * U_ + uq * 8;
    ((float4*)fo)[0] = make_float4(acc[0], acc[1], acc[2], acc[3]);
    ((float4*)fo)[1] = make_float4(acc[4], acc[5], acc[6], acc[7]);

    float s = 0.f, t = 0.f;
#pragma unroll
    for (int i = 0; i < 8; i++) {
        s += acc[i] * as_s[uq * 8 + i];
        t += acc[i] * as_n[uq * 8 + i];
    }
    s += __shfl_xor_sync(0xffffffffu, s, 1);
    t += __shfl_xor_sync(0xffffffffu, t, 1);
    s += __shfl_xor_sync(0xffffffffu, s, 2);
    t += __shfl_xor_sync(0xffffffffu, t, 2);
    if (uq == 0) {
        g_s[bh * N_ + n]  = s;
        g_t[bh * N_ + n]  = t;
        g_ea[bh * N_ + n] = expf(LEAKY * s);
        g_eb[bh * N_ + n] = expf(s);
    }
}

// ============================================================
// k2b: bucket + scatter only (smem-staged, coalesced copy-out).
// grid BH, block 1024 (4 elements/thread). ~68KB dynamic smem.
// ============================================================
__global__ void __launch_bounds__(1024, 1) k2b_bucket() {
    extern __shared__ unsigned char dsm[];
    float* tso_s  = (float*)dsm;                 // N
    float* w1_s   = tso_s + N_;                  // N
    float* w2_s   = w1_s + N_;                   // N
    int*   perm_s = (int*)(w2_s + N_);           // N
    int*   cnt    = perm_s + N_;                 // NB

    __shared__ float red[64];
    __shared__ int   wsum[32];
    __shared__ float slo, shi;

    const int bh = blockIdx.x;
    const int tid = threadIdx.x;
    const int lane = tid & 31, w = tid >> 5;

    float tv[4]; int bins[4];
    float mn = 1e30f, mx = -1e30f;
#pragma unroll
    for (int e = 0; e < 4; e++) {
        tv[e] = g_t[bh * N_ + tid * 4 + e];
        mn = fminf(mn, tv[e]); mx = fmaxf(mx, tv[e]);
    }
#pragma unroll
    for (int off = 16; off >= 1; off >>= 1) {
        mn = fminf(mn, __shfl_xor_sync(0xffffffffu, mn, off));
        mx = fmaxf(mx, __shfl_xor_sync(0xffffffffu, mx, off));
    }
    if (lane == 0) { red[w] = mn; red[32 + w] = mx; }
    cnt[tid] = 0;
    __syncthreads();
    if (w == 0) {
        float m1 = red[lane], m2 = red[32 + lane];
#pragma unroll
        for (int off = 16; off >= 1; off >>= 1) {
            m1 = fminf(m1, __shfl_xor_sync(0xffffffffu, m1, off));
            m2 = fmaxf(m2, __shfl_xor_sync(0xffffffffu, m2, off));
        }
        if (lane == 0) { slo = m1; shi = m2; }
    }
    __syncthreads();
    const float lo = slo;
    const float scale = (shi > lo) ? (float)NB_ * 0.999999f / (shi - lo) : 0.f;

#pragma unroll
    for (int e = 0; e < 4; e++) {
        int bi = (int)((tv[e] - lo) * scale);
        bi = min(NB_ - 1, max(0, bi));
        bins[e] = bi;
        atomicAdd(&cnt[bi], 1);
    }
    __syncthreads();

    const int cval = cnt[tid];
    int inc = cval;
#pragma unroll
    for (int off = 1; off < 32; off <<= 1) {
        const int o = __shfl_up_sync(0xffffffffu, inc, off);
        if (lane >= off) inc += o;
    }
    if (lane == 31) wsum[w] = inc;
    __syncthreads();
    if (tid == 0) {
        int run = 0;
#pragma unroll
        for (int k = 0; k < 32; k++) { const int xk = wsum[k]; wsum[k] = run; run += xk; }
    }
    __syncthreads();
    const int ex = inc - cval + wsum[w];
    g_binstart[bh * (NB_ + 1) + tid] = ex;
    cnt[tid] = ex;
    if (tid == 0) {
        g_binstart[bh * (NB_ + 1) + NB_] = N_;
        g_lo[bh] = lo; g_scale[bh] = scale;
    }
    __syncthreads();

#pragma unroll
    for (int e = 0; e < 4; e++) {
        const int pos = atomicAdd(&cnt[bins[e]], 1);
        perm_s[pos] = tid * 4 + e;
        tso_s[pos]  = tv[e];
        w1_s[pos]   = expf(tv[e]);
        w2_s[pos]   = expf(LEAKY * tv[e]);
    }
    __syncthreads();

#pragma unroll
    for (int k = 0; k < 4; k++) {
        const int i = tid + k * 1024;
        g_tso[bh * N_ + i]  = tso_s[i];
        g_w1so[bh * N_ + i] = w1_s[i];
        g_w2so[bh * N_ + i] = w2_s[i];
        g_perm[bh * N_ + i] = perm_s[i];
    }
}

// ============================================================
// k3: per-bin sums (warp -> bin, lane -> u). Massive parallelism
// hides gather latency (avg 4 elements/bin).
// grid (BH, NB/8), block 256.
// ============================================================
__global__ void __launch_bounds__(256) k3_bin_sums() {
    const int bh = blockIdx.x;
    const int w = threadIdx.x >> 5, lane = threadIdx.x & 31;
    const int bin = blockIdx.y * 8 + w;

    const int js = __ldg(&g_binstart[bh * (NB_ + 1) + bin]);
    const int je = __ldg(&g_binstart[bh * (NB_ + 1) + bin + 1]);
    const float* fe = g_feats + (size_t)bh * N_ * U_;

    float a1 = 0.f, a2 = 0.f, c1 = 0.f, c2 = 0.f;
    for (int j = js; j < je; j++) {
        const float w1 = __ldg(&g_w1so[bh * N_ + j]);
        const float w2 = __ldg(&g_w2so[bh * N_ + j]);
        const int p = __ldg(&g_perm[bh * N_ + j]);
        const float v = __ldg(&fe[p * U_ + lane]);
        a1 += w1 * v; a2 += w2 * v; c1 += w1; c2 += w2;
    }
    const size_t ti = ((size_t)bh * NB_ + bin) * U_ + lane;
    g_T1[ti] = a1;
    g_T2[ti] = a2;
    if (lane == 0) { g_C1[bh * NB_ + bin] = c1; g_C2[bh * NB_ + bin] = c2; }
}

// ============================================================
// k3b: two-level prefix. grid BH, block 1024 = 32 warps.
// Warp w = segment w; lane = u. All T reads coalesced+independent.
// ============================================================
__global__ void __launch_bounds__(1024, 1) k3b_scan() {
    __shared__ float seg1[NSEG_ * U_], seg2[NSEG_ * U_];
    __shared__ float segc1[NSEG_], segc2[NSEG_];
    const int bh = blockIdx.x;
    const int w = threadIdx.x >> 5, lane = threadIdx.x & 31;

    // vector within-segment exclusive prefix
    float r1 = 0.f, r2 = 0.f;
#pragma unroll 8
    for (int i = 0; i < 32; i++) {
        const size_t ti = ((size_t)bh * NB_ + w * 32 + i) * U_ + lane;
        const float a1 = g_T1[ti], a2 = g_T2[ti];
        g_O1[ti] = r1; g_O2[ti] = r2;
        r1 += a1; r2 += a2;
    }
    seg1[w * U_ + lane] = r1;
    seg2[w * U_ + lane] = r2;

    // scalar within-segment exclusive prefix (coalesced via lane=bin)
    const int cb = bh * NB_ + w * 32 + lane;
    const float c1 = g_C1[cb], c2 = g_C2[cb];
    float i1 = c1, i2 = c2;
#pragma unroll
    for (int off = 1; off < 32; off <<= 1) {
        const float x1 = __shfl_up_sync(0xffffffffu, i1, off);
        const float x2 = __shfl_up_sync(0xffffffffu, i2, off);
        if (lane >= off) { i1 += x1; i2 += x2; }
    }
    g_Sb1[cb] = i1 - c1;
    g_Sb2[cb] = i2 - c2;
    const float ct1 = __shfl_sync(0xffffffffu, i1, 31);
    const float ct2 = __shfl_sync(0xffffffffu, i2, 31);
    if (lane == 0) { segc1[w] = ct1; segc2[w] = ct2; }
    __syncthreads();

    // exclusive segment offsets
    float o1 = 0.f, o2 = 0.f, oc1 = 0.f, oc2 = 0.f;
    for (int s = 0; s < w; s++) {
        o1 += seg1[s * U_ + lane];
        o2 += seg2[s * U_ + lane];
        oc1 += segc1[s];
        oc2 += segc2[s];
    }
    const size_t si = ((size_t)bh * NSEG_ + w) * U_ + lane;
    g_Seg1[si] = o1;
    g_Seg2[si] = o2;
    if (lane == 0) {
        g_SegSb1[bh * NSEG_ + w] = oc1;
        g_SegSb2[bh * NSEG_ + w] = oc2;
    }
    if (w == 31) {
        g_Ptot1[bh * U_ + lane] = o1 + seg1[31 * U_ + lane];
        if (lane == 0) g_Stot1[bh] = oc1 + segc1[31];
    }
}

// ============================================================
// k4: per-node combine. warp -> one n, lane -> u. Pure load/FMA.
// grid BH*N/8, block 256
// ============================================================
__global__ void __launch_bounds__(256) k4_output(
        const float* __restrict__ biases, float* __restrict__ out) {
    const int gw = blockIdx.x * 8 + (threadIdx.x >> 5);
    const int lane = threadIdx.x & 31;
    const int bh = gw >> 12;        // / N_
    const int n = gw & (N_ - 1);
    const int b = bh >> 2, h = bh & (H_ - 1);

    const float c = g_s[bh * N_ + n];
    const float th = -c;
    const float lo = __ldg(&g_lo[bh]);
    const float scale = __ldg(&g_scale[bh]);
    int bq = (int)((th - lo) * scale);
    bq = min(NB_ - 1, max(0, bq));
    const int sq = bq >> 5;

    float p1 = __ldg(&g_O1[((size_t)bh * NB_ + bq) * U_ + lane])
             + __ldg(&g_Seg1[((size_t)bh * NSEG_ + sq) * U_ + lane]);
    float p2 = __ldg(&g_O2[((size_t)bh * NB_ + bq) * U_ + lane])
             + __ldg(&g_Seg2[((size_t)bh * NSEG_ + sq) * U_ + lane]);
    float s1 = __ldg(&g_Sb1[bh * NB_ + bq]) + __ldg(&g_SegSb1[bh * NSEG_ + sq]);
    float s2 = __ldg(&g_Sb2[bh * NB_ + bq]) + __ldg(&g_SegSb2[bh * NSEG_ + sq]);

    const int js = __ldg(&g_binstart[bh * (NB_ + 1) + bq]);
    const int je = __ldg(&g_binstart[bh * (NB_ + 1) + bq + 1]);
    const float* fe = g_feats + (size_t)bh * N_ * U_;
    for (int j = js; j < je; j++) {
        const float tv = __ldg(&g_tso[bh * N_ + j]);
        if (tv < th) {
            const float w1 = __ldg(&g_w1so[bh * N_ + j]);
            const float w2 = __ldg(&g_w2so[bh * N_ + j]);
            const int p = __ldg(&g_perm[bh * N_ + j]);
            const float v = __ldg(&fe[p * U_ + lane]);
            p1 += w1 * v; p2 += w2 * v; s1 += w1; s2 += w2;
        }
    }

    const float ea = __ldg(&g_ea[bh * N_ + n]);
    const float eb = __ldg(&g_eb[bh * N_ + n]);
    const float S1t = __ldg(&g_Stot1[bh]);
    const float pt1 = __ldg(&g_Ptot1[bh * U_ + lane]);

    const float Z = ea * s2 + eb * (S1t - s1);
    const float num = ea * p2 + eb * (pt1 - p1);
    const float val = num / Z + __ldg(&biases[h * U_ + lane]);

    out[((size_t)b * N_ + n) * (H_ * U_) + h * U_ + lane] = fmaxf(val, 0.f);
}

// ============================================================
extern "C" void kernel_launch(void* const* d_in, const int* in_sizes, int n_in,
                              void* d_out, int out_size) {
    const float* x      = (const float*)d_in[0];
    const float* kern   = (const float*)d_in[1];
    const float* att_s  = (const float*)d_in[2];
    const float* att_n  = (const float*)d_in[3];
    const float* biases = (const float*)d_in[4];
    float* out = (float*)d_out;

    const int k2b_smem = (4 * N_ + NB_) * 4;   // ~69.6 KB
    cudaFuncSetAttribute(k2b_bucket, cudaFuncAttributeMaxDynamicSharedMemorySize, k2b_smem);

    k1_feats<<<dim3(N_ / ROWS_, BH_), 256>>>(x, kern, att_s, att_n);
    k2b_bucket<<<BH_, 1024, k2b_smem>>>();
    k3_bin_sums<<<dim3(BH_, NB_ / 8), 256>>>();
    k3b_scan<<<BH_, 1024>>>();
    k4_output<<<(BH_ * N_) / 8, 256>>>(biases, out);
}